// round 7
// baseline (speedup 1.0000x reference)
#include <cuda_runtime.h>
#include <cuda_bf16.h>
#include <math.h>
#include <stdint.h>

// Problem constants
#define T_TOK   4096      // B*S = 2*2048
#define HDIM    1024
#define IDIM    4096
#define NEXP    8
#define MAXSLOT 9216      // 8192 pairs + per-expert pad to 128
#define MAXMB   72        // max m-blocks of 128 rows

// ---------------- static scratch (no runtime allocation) ----------------
__device__ float g_hdn [(size_t)MAXSLOT * IDIM];   // 151 MB  gate/up output
__device__ float g_pout[(size_t)MAXSLOT * HDIM];   // 37.7 MB down output (pre-weight)
__device__ int   g_perm[MAXSLOT];                  // slot -> token (-1 = pad)
__device__ int   g_tok2slot[T_TOK * 2];
__device__ float g_tokw   [T_TOK * 2];             // normalized top-2 weights
__device__ int   g_tokidx [T_TOK * 2];
__device__ int   g_counts [NEXP];
__device__ float g_load   [NEXP];                  // sum of softmax prob over selecting tokens
__device__ int   g_cursor [NEXP];
__device__ int   g_off    [NEXP];
__device__ int2  g_mblocks[80];                    // {row0, expert}
__device__ int   g_nmblocks;

// ---------------- small helpers ----------------
__device__ __forceinline__ uint32_t f2tf32(float f) {
    uint32_t u;
    asm volatile("cvt.rna.tf32.f32 %0, %1;\n" : "=r"(u) : "f"(f));
    return u;
}

__device__ __forceinline__ void mma8(float* d, const uint32_t* a, uint32_t b0, uint32_t b1) {
    asm volatile(
        "mma.sync.aligned.m16n8k8.row.col.f32.tf32.tf32.f32 "
        "{%0,%1,%2,%3}, {%4,%5,%6,%7}, {%8,%9}, {%0,%1,%2,%3};\n"
        : "+f"(d[0]), "+f"(d[1]), "+f"(d[2]), "+f"(d[3])
        : "r"(a[0]), "r"(a[1]), "r"(a[2]), "r"(a[3]), "r"(b0), "r"(b1));
}

__device__ __forceinline__ void cp16(uint32_t dst, const void* src, int bytes) {
    asm volatile("cp.async.cg.shared.global [%0], [%1], 16, %2;\n"
                 :: "r"(dst), "l"(src), "r"(bytes));
}
__device__ __forceinline__ void cp_commit() { asm volatile("cp.async.commit_group;\n"); }
template <int N>
__device__ __forceinline__ void cp_wait() { asm volatile("cp.async.wait_group %0;\n" :: "n"(N)); }

// ---------------- kernel 1: init ----------------
__global__ void moe_init() {
    int tid = threadIdx.x;
    for (int i = tid; i < MAXSLOT; i += 256) g_perm[i] = -1;
    if (tid < NEXP) {
        g_counts[tid] = 0;
        g_load[tid]   = 0.f;
        g_cursor[tid] = 0;
    }
}

// ---------------- kernel 2: router (exact fp32) ----------------
// 512 blocks x 256 threads; one warp per token.
__global__ void moe_router(const float* __restrict__ x, const float* __restrict__ gw) {
    const int warp = threadIdx.x >> 5;
    const int lane = threadIdx.x & 31;
    const int t = blockIdx.x * 8 + warp;

    const int e   = lane & 7;       // expert handled by this lane (replicated x4)
    const int seg = lane >> 3;      // 4 segments of 256 of the H dim
    const float* xr  = x  + (size_t)t * HDIM + seg * 256;
    const float* gwp = gw + (size_t)(seg * 256) * NEXP + e;
    float acc = 0.f;
    #pragma unroll 8
    for (int j = 0; j < 256; j++) acc += xr[j] * gwp[j * NEXP];
    acc += __shfl_xor_sync(0xffffffffu, acc, 8);
    acc += __shfl_xor_sync(0xffffffffu, acc, 16);

    float lg[8];
    #pragma unroll
    for (int i = 0; i < 8; i++) lg[i] = __shfl_sync(0xffffffffu, acc, i);

    if (lane == 0) {
        // softmax over 8
        float m = lg[0];
        #pragma unroll
        for (int i = 1; i < 8; i++) m = fmaxf(m, lg[i]);
        float p[8], s = 0.f;
        #pragma unroll
        for (int i = 0; i < 8; i++) { p[i] = expf(lg[i] - m); s += p[i]; }
        float inv = 1.f / s;
        #pragma unroll
        for (int i = 0; i < 8; i++) p[i] *= inv;
        // top-2, first index wins ties (matches jax top_k)
        int i1 = 0;
        #pragma unroll
        for (int i = 1; i < 8; i++) if (p[i] > p[i1]) i1 = i;
        int i2 = (i1 == 0) ? 1 : 0;
        #pragma unroll
        for (int i = 0; i < 8; i++) if (i != i1 && p[i] > p[i2]) i2 = i;
        float denom = p[i1] + p[i2];
        float w1 = p[i1] / denom, w2 = p[i2] / denom;

        g_tokidx[2 * t]     = i1;
        g_tokidx[2 * t + 1] = i2;
        g_tokw[2 * t]       = w1;
        g_tokw[2 * t + 1]   = w2;
        atomicAdd(&g_counts[i1], 1);
        atomicAdd(&g_counts[i2], 1);
        atomicAdd(&g_load[i1], p[i1]);
        atomicAdd(&g_load[i2], p[i2]);
    }
}

// ---------------- kernel 3: scheduler + aux loss ----------------
__global__ void moe_sched(float* aux_out, int has_aux) {
    if (threadIdx.x == 0) {
        int off = 0, nm = 0;
        for (int e = 0; e < NEXP; e++) {
            g_off[e] = off;
            int nb = (g_counts[e] + 127) >> 7;
            for (int b = 0; b < nb; b++) {
                g_mblocks[nm] = make_int2(off + b * 128, e);
                nm++;
            }
            off += nb << 7;
        }
        g_nmblocks = nm;
        if (has_aux) {
            float aux = 0.f;
            for (int e = 0; e < NEXP; e++)
                aux += (g_load[e] / (float)T_TOK) * ((float)g_counts[e] / (float)(T_TOK * 2));
            aux *= (float)NEXP * 0.001f;
            *aux_out = aux;
        }
    }
}

// ---------------- kernel 4: scatter tokens into expert slots ----------------
__global__ void moe_scatter() {
    int t = blockIdx.x * 256 + threadIdx.x;
    if (t < T_TOK) {
        #pragma unroll
        for (int k = 0; k < 2; k++) {
            int e = g_tokidx[2 * t + k];
            int pos = atomicAdd(&g_cursor[e], 1);
            int slot = g_off[e] + pos;
            g_perm[slot] = t;
            g_tok2slot[2 * t + k] = slot;
        }
    }
}

// ---------------- kernels 5/6: tf32 tensor-core GEMM ----------------
// NMATS==2: A = x rows gathered via g_perm; B0/B1 = wg/wu; out = silu(g)*u -> g_hdn
// NMATS==1: A = g_hdn slot rows;          B0 = wd;        out -> g_pout
// Block tile 128x64, BK=32, 256 threads (8 warps, warp tile 32x32).
// Padded smem (A stride 36, B stride 72) -> conflict-free tf32 fragment loads.
template <int NMATS, int KDIM, int NDIM>
__global__ void __launch_bounds__(256)
gemm_tf32_kernel(const float* __restrict__ Aglob,
                 const float* __restrict__ B0g,
                 const float* __restrict__ B1g)
{
    constexpr int BM = 128, BN = 64, BK = 32;
    constexpr int AP = 36, BP = 72;
    constexpr int ASTG = BM * AP;           // floats per A stage
    constexpr int BSTG = NMATS * BK * BP;   // floats per B stage
    constexpr int KT = KDIM / BK;

    const int mb = blockIdx.y;
    if (mb >= g_nmblocks) return;
    const int row0 = g_mblocks[mb].x;
    const int e    = g_mblocks[mb].y;
    const int n0   = blockIdx.x * BN;

    const float* B0 = B0g + (size_t)e * KDIM * NDIM;
    const float* B1 = (NMATS == 2) ? (B1g + (size_t)e * KDIM * NDIM) : B0g;
    const float* Ab = (NMATS == 2) ? Aglob : g_hdn;
    float* Out      = (NMATS == 2) ? g_hdn : g_pout;

    extern __shared__ float sm[];
    float* As = sm;
    float* Bs = sm + 2 * ASTG;
    const uint32_t as_addr = (uint32_t)__cvta_generic_to_shared(As);
    const uint32_t bs_addr = (uint32_t)__cvta_generic_to_shared(Bs);

    const int tid  = threadIdx.x;
    const int lane = tid & 31;
    const int wid  = tid >> 5;
    const int wm   = wid >> 1;   // 0..3
    const int wn   = wid & 1;    // 0..1
    const int lr   = lane >> 2;  // groupID 0..7
    const int lc   = lane & 3;   // tid-in-group 0..3

    // A loader: 4 x 16B chunks per thread
    const int ar = tid >> 3;   // base row 0..31
    const int ac = tid & 7;    // chunk in row
    const float* aptr[4];
    uint32_t adst[4];
    #pragma unroll
    for (int i = 0; i < 4; i++) {
        int r = ar + 32 * i;
        int gr = (NMATS == 2) ? g_perm[row0 + r] : (row0 + r);
        aptr[i] = (gr >= 0) ? (Ab + (size_t)gr * KDIM + ac * 4) : nullptr;
        adst[i] = as_addr + (uint32_t)((r * AP + ac * 4) * 4);
    }
    // B loader: NMATS*2 x 16B chunks per thread
    constexpr int BPT = (NMATS * BK * (BN / 4)) / 256;  // 4 or 2
    const float* bptr[BPT];
    uint32_t bdst[BPT];
    #pragma unroll
    for (int i = 0; i < BPT; i++) {
        int c   = tid + 256 * i;
        int mat = (NMATS == 2) ? (c >> 9) : 0;
        int rem = (NMATS == 2) ? (c & 511) : c;
        int kr  = rem >> 4;
        int nc  = rem & 15;
        const float* bb = (mat == 0) ? B0 : B1;
        bptr[i] = bb + (size_t)kr * NDIM + n0 + nc * 4;
        bdst[i] = bs_addr + (uint32_t)((mat * BK * BP + kr * BP + nc * 4) * 4);
    }

    auto load_stage = [&](int stg, int k0) {
        uint32_t aoff = (uint32_t)(stg * ASTG * 4);
        #pragma unroll
        for (int i = 0; i < 4; i++)
            cp16(adst[i] + aoff, aptr[i] ? (const void*)(aptr[i] + k0) : (const void*)Ab,
                 aptr[i] ? 16 : 0);
        uint32_t boff = (uint32_t)(stg * BSTG * 4);
        #pragma unroll
        for (int i = 0; i < BPT; i++)
            cp16(bdst[i] + boff, bptr[i] + (size_t)k0 * NDIM, 16);
    };

    float acc0[2][4][4];
    float acc1[2][4][4];
    #pragma unroll
    for (int a = 0; a < 2; a++)
        #pragma unroll
        for (int b = 0; b < 4; b++)
            #pragma unroll
            for (int c = 0; c < 4; c++) { acc0[a][b][c] = 0.f; acc1[a][b][c] = 0.f; }

    load_stage(0, 0);
    cp_commit();

    for (int kt = 0; kt < KT; kt++) {
        if (kt + 1 < KT) {
            load_stage((kt + 1) & 1, (kt + 1) * BK);
            cp_commit();
            cp_wait<1>();
        } else {
            cp_wait<0>();
        }
        __syncthreads();

        const int stg = kt & 1;
        const float* Asb = As + stg * ASTG;
        const float* Bsb = Bs + stg * BSTG;

        #pragma unroll
        for (int kk = 0; kk < 4; kk++) {
            uint32_t afr[2][4];
            #pragma unroll
            for (int mt = 0; mt < 2; mt++) {
                const float* ap = Asb + (wm * 32 + mt * 16 + lr) * AP + kk * 8 + lc;
                afr[mt][0] = f2tf32(ap[0]);
                afr[mt][1] = f2tf32(ap[8 * AP]);
                afr[mt][2] = f2tf32(ap[4]);
                afr[mt][3] = f2tf32(ap[8 * AP + 4]);
            }
            #pragma unroll
            for (int nt = 0; nt < 4; nt++) {
                const float* bp = Bsb + (kk * 8 + lc) * BP + wn * 32 + nt * 8 + lr;
                uint32_t b00 = f2tf32(bp[0]);
                uint32_t b01 = f2tf32(bp[4 * BP]);
                #pragma unroll
                for (int mt = 0; mt < 2; mt++) mma8(acc0[mt][nt], afr[mt], b00, b01);
                if (NMATS == 2) {
                    const float* bq = bp + BK * BP;
                    uint32_t b10 = f2tf32(bq[0]);
                    uint32_t b11 = f2tf32(bq[4 * BP]);
                    #pragma unroll
                    for (int mt = 0; mt < 2; mt++) mma8(acc1[mt][nt], afr[mt], b10, b11);
                }
            }
        }
        __syncthreads();
    }

    // epilogue
    #pragma unroll
    for (int mt = 0; mt < 2; mt++) {
        #pragma unroll
        for (int nt = 0; nt < 4; nt++) {
            int r = row0 + wm * 32 + mt * 16 + lr;
            int c = n0 + wn * 32 + nt * 8 + lc * 2;
            if (NMATS == 2) {
                float g0 = acc0[mt][nt][0], g1 = acc0[mt][nt][1];
                float g2 = acc0[mt][nt][2], g3 = acc0[mt][nt][3];
                float u0 = acc1[mt][nt][0], u1 = acc1[mt][nt][1];
                float u2 = acc1[mt][nt][2], u3 = acc1[mt][nt][3];
                float2 v0, v1;
                v0.x = g0 * u0 / (1.f + expf(-g0));
                v0.y = g1 * u1 / (1.f + expf(-g1));
                v1.x = g2 * u2 / (1.f + expf(-g2));
                v1.y = g3 * u3 / (1.f + expf(-g3));
                *(float2*)&Out[(size_t)r * NDIM + c]       = v0;
                *(float2*)&Out[(size_t)(r + 8) * NDIM + c] = v1;
            } else {
                float2 v0 = make_float2(acc0[mt][nt][0], acc0[mt][nt][1]);
                float2 v1 = make_float2(acc0[mt][nt][2], acc0[mt][nt][3]);
                *(float2*)&Out[(size_t)r * NDIM + c]       = v0;
                *(float2*)&Out[(size_t)(r + 8) * NDIM + c] = v1;
            }
        }
    }
}

// ---------------- kernel 7: deterministic combine ----------------
__global__ void moe_combine(float* __restrict__ out) {
    const int t = blockIdx.x;
    const int s0 = g_tok2slot[2 * t];
    const int s1 = g_tok2slot[2 * t + 1];
    const float w0 = g_tokw[2 * t];
    const float w1 = g_tokw[2 * t + 1];
    const float* p0 = g_pout + (size_t)s0 * HDIM;
    const float* p1 = g_pout + (size_t)s1 * HDIM;
    float* o = out + (size_t)t * HDIM;
    #pragma unroll
    for (int i = 0; i < 4; i++) {
        int h = threadIdx.x + i * 256;
        o[h] = w0 * p0[h] + w1 * p1[h];
    }
}

// ---------------- launch ----------------
extern "C" void kernel_launch(void* const* d_in, const int* in_sizes, int n_in,
                              void* d_out, int out_size) {
    const float* x  = (const float*)d_in[0];   // [T, H]
    const float* gw = (const float*)d_in[1];   // [H, E]
    const float* wg = (const float*)d_in[2];   // [E, H, I]
    const float* wu = (const float*)d_in[3];   // [E, H, I]
    const float* wd = (const float*)d_in[4];   // [E, I, H]
    float* out = (float*)d_out;
    const int base = T_TOK * HDIM;

    const size_t sm1 = (size_t)2 * (128 * 36 + 2 * 32 * 72) * 4;  // 73728 B
    const size_t sm2 = (size_t)2 * (128 * 36 + 1 * 32 * 72) * 4;  // 55296 B
    cudaFuncSetAttribute(gemm_tf32_kernel<2, HDIM, IDIM>,
                         cudaFuncAttributeMaxDynamicSharedMemorySize, (int)sm1);
    cudaFuncSetAttribute(gemm_tf32_kernel<1, IDIM, HDIM>,
                         cudaFuncAttributeMaxDynamicSharedMemorySize, (int)sm2);

    moe_init<<<1, 256>>>();
    moe_router<<<T_TOK / 8, 256>>>(x, gw);
    moe_sched<<<1, 32>>>(out + base, (out_size > base) ? 1 : 0);
    moe_scatter<<<T_TOK / 256, 256>>>();
    gemm_tf32_kernel<2, HDIM, IDIM><<<dim3(IDIM / 64, MAXMB), 256, sm1>>>(x, wg, wu);
    gemm_tf32_kernel<1, IDIM, HDIM><<<dim3(HDIM / 64, MAXMB), 256, sm2>>>(nullptr, wd, nullptr);
    moe_combine<<<T_TOK, 256>>>(out);
}